// round 7
// baseline (speedup 1.0000x reference)
#include <cuda_runtime.h>
#include <cuda_bf16.h>
#include <cstdint>

typedef unsigned long long u64;

#define TB 1024
#define BB 4
#define ROWB 64u                 // bytes per bf16 row: 32 bf16, permuted-granule layout
#define ARR  16384u              // 256 * ROWB
#define DSMEM_BYTES (4 * 16384)  // QH | QL | KH | KL

// Granule layout: row r holds 4 x uint4; granule i = bf16 pairs {i, i+4, i+8, i+12}.
// One LDS.128 at (row*64 + cq*16) yields the MMA fragment regs for BOTH K16 halves.

// ---------------- helpers ----------------
static __device__ __forceinline__ u64 pack2(float lo, float hi) {
    u64 r; asm("mov.b64 %0, {%1, %2};" : "=l"(r) : "f"(lo), "f"(hi)); return r;
}
static __device__ __forceinline__ void unpack2(u64 p, float& lo, float& hi) {
    asm("mov.b64 {%0, %1}, %2;" : "=f"(lo), "=f"(hi) : "l"(p));
}
static __device__ __forceinline__ u64 ffma2(u64 a, u64 b, u64 c) {
    u64 d; asm("fma.rn.f32x2 %0, %1, %2, %3;" : "=l"(d) : "l"(a), "l"(b), "l"(c)); return d;
}
static __device__ __forceinline__ float ex2f(float v) {
    float y; asm("ex2.approx.ftz.f32 %0, %1;" : "=f"(y) : "f"(v)); return y;
}
static __device__ __forceinline__ float dot32(const float* wrow, const u64* win2) {
    u64 acc = 0ull;
    const ulonglong2* w2 = (const ulonglong2*)wrow;
    #pragma unroll
    for (int i = 0; i < 8; i++) {
        ulonglong2 w = w2[i];
        acc = ffma2(win2[2 * i + 0], w.x, acc);
        acc = ffma2(win2[2 * i + 1], w.y, acc);
    }
    float lo, hi; unpack2(acc, lo, hi);
    return lo + hi;
}
static __device__ __forceinline__ void bsplit(float v, uint16_t& hi, uint16_t& lo) {
    __nv_bfloat16 h = __float2bfloat16(v);
    __nv_bfloat16 l = __float2bfloat16(v - __bfloat162float(h));
    hi = __bfloat16_as_ushort(h);
    lo = __bfloat16_as_ushort(l);
}
// m16n8k16 row.col f32.bf16.bf16.f32, D += A*B
static __device__ __forceinline__ void mma16816(float* d, uint32_t a0, uint32_t a1,
                                                uint32_t a2, uint32_t a3,
                                                uint32_t b0, uint32_t b1) {
    asm("mma.sync.aligned.m16n8k16.row.col.f32.bf16.bf16.f32 "
        "{%0,%1,%2,%3}, {%4,%5,%6,%7}, {%8,%9}, {%0,%1,%2,%3};"
        : "+f"(d[0]), "+f"(d[1]), "+f"(d[2]), "+f"(d[3])
        : "r"(a0), "r"(a1), "r"(a2), "r"(a3), "r"(b0), "r"(b1));
}

// ---------------- kernel ----------------
__global__ void __launch_bounds__(256, 2)
csa_mma_kernel(const float* __restrict__ x,
               const float* __restrict__ kw,  const float* __restrict__ kbias,
               const float* __restrict__ kg,  const float* __restrict__ kbeta,
               const float* __restrict__ qw,  const float* __restrict__ qbias,
               const float* __restrict__ qg,  const float* __restrict__ qbeta,
               float* __restrict__ out)
{
    extern __shared__ char dsm[];
    __shared__ __align__(16) float s_wq[32 * 32];
    __shared__ __align__(16) float s_wk[32 * 32];
    __shared__ float s_bq[32], s_bk[32];
    __shared__ __align__(8) float s_v[256];

    char* QH = dsm;
    char* QL = dsm + ARR;
    char* KH = dsm + 2 * ARR;
    char* KL = dsm + 3 * ARR;

    const int t   = blockIdx.x;
    const int b   = blockIdx.y;
    const int tid = threadIdx.x;
    const int w   = tid >> 5;
    const int l   = tid & 31;
    const int g   = l >> 2;    // fragment row group
    const int cq  = l & 3;     // quad col id (granule index)

    // ---- fold BN into weights/bias ----
    const float inv = rsqrtf(1.0f + 1e-5f);
    for (int i = tid; i < 32 * 32; i += 256) {
        int s = i >> 5;
        s_wq[i] = qw[i] * (qg[s] * inv);
        s_wk[i] = kw[i] * (kg[s] * inv);
    }
    if (tid < 32) {
        s_bq[tid] = qbias[tid] * (qg[tid] * inv) + qbeta[tid];
        s_bk[tid] = kbias[tid] * (kg[tid] * inv) + kbeta[tid];
    }

    // ---- causal window (x is L2-resident) ----
    float win[32];
    {
        const float* xrow = x + ((size_t)(b * 256 + tid)) * TB;
        #pragma unroll
        for (int d = 0; d < 32; d++) {
            int tau = t - 31 + d;
            win[d] = (tau >= 0) ? xrow[tau] : 0.0f;
        }
    }
    s_v[tid] = win[31];
    __syncthreads();

    // ---- projections + bf16 split -> smem (permuted granules) ----
    {
        u64 win2[16];
        #pragma unroll
        for (int i = 0; i < 16; i++) win2[i] = pack2(win[2 * i], win[2 * i + 1]);

        const float qscale = 0.17677669529663687f * 1.4426950408889634f; // (1/sqrt32)*log2(e)
        uint32_t qhp[16], qlp[16], khp[16], klp[16];
        #pragma unroll
        for (int s2 = 0; s2 < 16; s2++) {
            int sA = 2 * s2, sB = sA + 1;
            float qa = fmaxf(dot32(s_wq + sA * 32, win2) + s_bq[sA], 0.0f) * qscale;
            float qb = fmaxf(dot32(s_wq + sB * 32, win2) + s_bq[sB], 0.0f) * qscale;
            float ka = fmaxf(dot32(s_wk + sA * 32, win2) + s_bk[sA], 0.0f);
            float kb = fmaxf(dot32(s_wk + sB * 32, win2) + s_bk[sB], 0.0f);
            uint16_t h0, l0, h1, l1;
            bsplit(qa, h0, l0); bsplit(qb, h1, l1);
            qhp[s2] = (uint32_t)h0 | ((uint32_t)h1 << 16);
            qlp[s2] = (uint32_t)l0 | ((uint32_t)l1 << 16);
            bsplit(ka, h0, l0); bsplit(kb, h1, l1);
            khp[s2] = (uint32_t)h0 | ((uint32_t)h1 << 16);
            klp[s2] = (uint32_t)l0 | ((uint32_t)l1 << 16);
        }
        uint4* qhr = (uint4*)(QH + tid * ROWB);
        uint4* qlr = (uint4*)(QL + tid * ROWB);
        uint4* khr = (uint4*)(KH + tid * ROWB);
        uint4* klr = (uint4*)(KL + tid * ROWB);
        #pragma unroll
        for (int i = 0; i < 4; i++) {
            qhr[i] = make_uint4(qhp[i], qhp[i + 4], qhp[i + 8], qhp[i + 12]);
            qlr[i] = make_uint4(qlp[i], qlp[i + 4], qlp[i + 8], qlp[i + 12]);
            khr[i] = make_uint4(khp[i], khp[i + 4], khp[i + 8], khp[i + 12]);
            klr[i] = make_uint4(klp[i], klp[i + 4], klp[i + 8], klp[i + 12]);
        }
    }
    __syncthreads();

    // ---- A fragments, held whole loop: aqh/aql[mt][k2][reg] ----
    // granule(row r, slot cq): pairs {cq, cq+4, cq+8, cq+12}
    //   -> k2=0 frag regs from .x/.y, k2=1 from .z/.w (rows g and g+8)
    uint32_t aqh[2][2][4], aql[2][2][4];
    #pragma unroll
    for (int mt = 0; mt < 2; mt++) {
        uint32_t r0off = (uint32_t)(32 * w + 16 * mt + g) * ROWB + (uint32_t)cq * 16u;
        uint4 uh0 = *(const uint4*)(QH + r0off);
        uint4 uh1 = *(const uint4*)(QH + r0off + 8 * ROWB);
        uint4 ul0 = *(const uint4*)(QL + r0off);
        uint4 ul1 = *(const uint4*)(QL + r0off + 8 * ROWB);
        aqh[mt][0][0] = uh0.x; aqh[mt][0][1] = uh1.x; aqh[mt][0][2] = uh0.y; aqh[mt][0][3] = uh1.y;
        aqh[mt][1][0] = uh0.z; aqh[mt][1][1] = uh1.z; aqh[mt][1][2] = uh0.w; aqh[mt][1][3] = uh1.w;
        aql[mt][0][0] = ul0.x; aql[mt][0][1] = ul1.x; aql[mt][0][2] = ul0.y; aql[mt][0][3] = ul1.y;
        aql[mt][1][0] = ul0.z; aql[mt][1][1] = ul1.z; aql[mt][1][2] = ul0.w; aql[mt][1][3] = ul1.w;
    }

    float stM[4], stD[4], stN[4];
    #pragma unroll
    for (int r = 0; r < 4; r++) { stM[r] = -1e30f; stD[r] = 0.0f; stN[r] = 0.0f; }

    // B row base for this thread: row = 16*ch + 8*nt + g, slot cq
    const char* KHg = KH + (uint32_t)g * ROWB + (uint32_t)cq * 16u;
    const char* KLg = KL + (uint32_t)g * ROWB + (uint32_t)cq * 16u;

    // double-buffered B: [nt] hi, lo
    uint4 bh[2], blo[2], nbh[2], nbl[2];
    #pragma unroll
    for (int nt = 0; nt < 2; nt++) {
        bh[nt]  = *(const uint4*)(KHg + (uint32_t)(8 * nt) * ROWB);
        blo[nt] = *(const uint4*)(KLg + (uint32_t)(8 * nt) * ROWB);
    }

    #pragma unroll 1
    for (int ch = 0; ch < 16; ch++) {
        // prefetch next chunk's B (clamped re-load on last iter)
        const uint32_t nch = (ch < 15) ? (uint32_t)(ch + 1) : 15u;
        #pragma unroll
        for (int nt = 0; nt < 2; nt++) {
            nbh[nt] = *(const uint4*)(KHg + (nch * 16u + 8u * nt) * ROWB);
            nbl[nt] = *(const uint4*)(KLg + (nch * 16u + 8u * nt) * ROWB);
        }

        float2 v0 = *(const float2*)&s_v[16 * ch + 2 * cq];
        float2 v1 = *(const float2*)&s_v[16 * ch + 8 + 2 * cq];

        float acc[2][2][4];
        #pragma unroll
        for (int mt = 0; mt < 2; mt++)
            #pragma unroll
            for (int nt = 0; nt < 2; nt++) {
                float* a = acc[mt][nt];
                a[0] = a[1] = a[2] = a[3] = 0.0f;
                // qh*kh (k0,k1), qh*kl, ql*kh  — exact to ~1e-5
                mma16816(a, aqh[mt][0][0], aqh[mt][0][1], aqh[mt][0][2], aqh[mt][0][3], bh[nt].x,  bh[nt].y);
                mma16816(a, aqh[mt][1][0], aqh[mt][1][1], aqh[mt][1][2], aqh[mt][1][3], bh[nt].z,  bh[nt].w);
                mma16816(a, aqh[mt][0][0], aqh[mt][0][1], aqh[mt][0][2], aqh[mt][0][3], blo[nt].x, blo[nt].y);
                mma16816(a, aqh[mt][1][0], aqh[mt][1][1], aqh[mt][1][2], aqh[mt][1][3], blo[nt].z, blo[nt].w);
                mma16816(a, aql[mt][0][0], aql[mt][0][1], aql[mt][0][2], aql[mt][0][3], bh[nt].x,  bh[nt].y);
                mma16816(a, aql[mt][1][0], aql[mt][1][1], aql[mt][1][2], aql[mt][1][3], bh[nt].z,  bh[nt].w);
            }

        // flash update: 4 logical rows per thread, 4 cols each
        #pragma unroll
        for (int mt = 0; mt < 2; mt++)
            #pragma unroll
            for (int i = 0; i < 2; i++) {
                int r = mt * 2 + i;
                float s0 = acc[mt][0][2 * i + 0];
                float s1 = acc[mt][0][2 * i + 1];
                float s2 = acc[mt][1][2 * i + 0];
                float s3 = acc[mt][1][2 * i + 1];
                float mx = fmaxf(fmaxf(s0, s1), fmaxf(s2, s3));
                float Mn = fmaxf(stM[r], mx);
                float corr = ex2f(stM[r] - Mn);
                float e0 = ex2f(s0 - Mn);
                float e1 = ex2f(s1 - Mn);
                float e2 = ex2f(s2 - Mn);
                float e3 = ex2f(s3 - Mn);
                stD[r] = stD[r] * corr + ((e0 + e1) + (e2 + e3));
                stN[r] = stN[r] * corr + (e0 * v0.x + e1 * v0.y + e2 * v1.x + e3 * v1.y);
                stM[r] = Mn;
            }

        bh[0] = nbh[0]; bh[1] = nbh[1];
        blo[0] = nbl[0]; blo[1] = nbl[1];
    }

    // ---- quad merge (cols) + write ----
    #pragma unroll
    for (int r = 0; r < 4; r++) {
        #pragma unroll
        for (int off = 1; off <= 2; off <<= 1) {
            float pm = __shfl_xor_sync(0xffffffffu, stM[r], off);
            float pd = __shfl_xor_sync(0xffffffffu, stD[r], off);
            float pn = __shfl_xor_sync(0xffffffffu, stN[r], off);
            float M  = fmaxf(stM[r], pm);
            float ca = ex2f(stM[r] - M), cb = ex2f(pm - M);
            stD[r] = stD[r] * ca + pd * cb;
            stN[r] = stN[r] * ca + pn * cb;
            stM[r] = M;
        }
    }
    if (cq == 0) {
        #pragma unroll
        for (int r = 0; r < 4; r++) {
            int row = 32 * w + (r >> 1) * 16 + (r & 1) * 8 + g;
            out[((size_t)(b * 256 + row)) * TB + t] = s_v[row] + stN[r] / stD[r];
        }
    }
}

extern "C" void kernel_launch(void* const* d_in, const int* in_sizes, int n_in,
                              void* d_out, int out_size) {
    const float* x    = (const float*)d_in[0];
    const float* kw   = (const float*)d_in[1];
    const float* kb   = (const float*)d_in[2];
    const float* kg   = (const float*)d_in[3];
    const float* kbe  = (const float*)d_in[4];
    const float* qw   = (const float*)d_in[5];
    const float* qb   = (const float*)d_in[6];
    const float* qg   = (const float*)d_in[7];
    const float* qbe  = (const float*)d_in[8];
    float* o = (float*)d_out;

    cudaFuncSetAttribute(csa_mma_kernel, cudaFuncAttributeMaxDynamicSharedMemorySize, DSMEM_BYTES);
    dim3 grid(TB, BB);
    csa_mma_kernel<<<grid, 256, DSMEM_BYTES>>>(x, kw, kb, kg, kbe, qw, qb, qg, qbe, o);
}

// round 8
// speedup vs baseline: 1.2529x; 1.2529x over previous
#include <cuda_runtime.h>
#include <cuda_bf16.h>
#include <cstdint>

typedef unsigned long long u64;

#define TB 1024
#define BB 4
#define ROWB 64u                 // bytes per bf16 row: 32 bf16, permuted-granule layout
#define ARR  16384u              // 256 * ROWB
#define DSMEM_BYTES (4 * 16384)  // QH | QL | KH | KL
#define XROW 33                  // s_x row stride in floats (conflict-free)

// Granule layout: row r holds 4 x uint4; granule i = bf16 pairs {i, i+4, i+8, i+12}.
// One LDS.128 at (row*64 + cq*16) yields the MMA fragment regs for BOTH K16 halves.

// ---------------- helpers ----------------
static __device__ __forceinline__ u64 pack2(float lo, float hi) {
    u64 r; asm("mov.b64 %0, {%1, %2};" : "=l"(r) : "f"(lo), "f"(hi)); return r;
}
static __device__ __forceinline__ void unpack2(u64 p, float& lo, float& hi) {
    asm("mov.b64 {%0, %1}, %2;" : "=f"(lo), "=f"(hi) : "l"(p));
}
static __device__ __forceinline__ u64 ffma2(u64 a, u64 b, u64 c) {
    u64 d; asm("fma.rn.f32x2 %0, %1, %2, %3;" : "=l"(d) : "l"(a), "l"(b), "l"(c)); return d;
}
static __device__ __forceinline__ float ex2f(float v) {
    float y; asm("ex2.approx.ftz.f32 %0, %1;" : "=f"(y) : "f"(v)); return y;
}
static __device__ __forceinline__ float dot32(const float* wrow, const u64* win2) {
    u64 acc = 0ull;
    const ulonglong2* w2 = (const ulonglong2*)wrow;
    #pragma unroll
    for (int i = 0; i < 8; i++) {
        ulonglong2 w = w2[i];
        acc = ffma2(win2[2 * i + 0], w.x, acc);
        acc = ffma2(win2[2 * i + 1], w.y, acc);
    }
    float lo, hi; unpack2(acc, lo, hi);
    return lo + hi;
}
static __device__ __forceinline__ void bsplit(float v, uint16_t& hi, uint16_t& lo) {
    __nv_bfloat16 h = __float2bfloat16(v);
    __nv_bfloat16 l = __float2bfloat16(v - __bfloat162float(h));
    hi = __bfloat16_as_ushort(h);
    lo = __bfloat16_as_ushort(l);
}
// m16n8k16 row.col f32.bf16.bf16.f32, D += A*B
static __device__ __forceinline__ void mma16816(float* d, uint32_t a0, uint32_t a1,
                                                uint32_t a2, uint32_t a3,
                                                uint32_t b0, uint32_t b1) {
    asm("mma.sync.aligned.m16n8k16.row.col.f32.bf16.bf16.f32 "
        "{%0,%1,%2,%3}, {%4,%5,%6,%7}, {%8,%9}, {%0,%1,%2,%3};"
        : "+f"(d[0]), "+f"(d[1]), "+f"(d[2]), "+f"(d[3])
        : "r"(a0), "r"(a1), "r"(a2), "r"(a3), "r"(b0), "r"(b1));
}

// ---------------- kernel ----------------
__global__ void __launch_bounds__(256, 2)
csa_mma_kernel(const float* __restrict__ x,
               const float* __restrict__ kw,  const float* __restrict__ kbias,
               const float* __restrict__ kg,  const float* __restrict__ kbeta,
               const float* __restrict__ qw,  const float* __restrict__ qbias,
               const float* __restrict__ qg,  const float* __restrict__ qbeta,
               float* __restrict__ out)
{
    extern __shared__ char dsm[];
    __shared__ __align__(16) float s_wq[32 * 32];
    __shared__ __align__(16) float s_wk[32 * 32];
    __shared__ float s_bq[32], s_bk[32];
    __shared__ __align__(8) float s_v[256];
    __shared__ __align__(16) float s_x[256 * XROW];   // staged windows, stride 33

    char* QH = dsm;
    char* QL = dsm + ARR;
    char* KH = dsm + 2 * ARR;
    char* KL = dsm + 3 * ARR;

    const int t   = blockIdx.x;
    const int b   = blockIdx.y;
    const int tid = threadIdx.x;
    const int w   = tid >> 5;
    const int l   = tid & 31;
    const int g   = l >> 2;    // fragment row group
    const int cq  = l & 3;     // quad col id (granule index)

    // ---- fold BN into weights/bias ----
    const float inv = rsqrtf(1.0f + 1e-5f);
    for (int i = tid; i < 32 * 32; i += 256) {
        int s = i >> 5;
        s_wq[i] = qw[i] * (qg[s] * inv);
        s_wk[i] = kw[i] * (kg[s] * inv);
    }
    if (tid < 32) {
        s_bq[tid] = qbias[tid] * (qg[tid] * inv) + qbeta[tid];
        s_bk[tid] = kbias[tid] * (kg[tid] * inv) + kbeta[tid];
    }

    // ---- stage all windows coalesced: lane = time offset -> contiguous 128B ----
    {
        const float* xb = x + ((size_t)b * 256) * TB;
        #pragma unroll
        for (int i = tid; i < 256 * 32; i += 256) {
            int c = i >> 5, d = i & 31;
            int tau = t - 31 + d;
            s_x[c * XROW + d] = (tau >= 0) ? xb[(size_t)c * TB + tau] : 0.0f;
        }
    }
    __syncthreads();

    // ---- window from smem (conflict-free: bank = lane + d) ----
    float win[32];
    {
        const float* xr = s_x + tid * XROW;
        #pragma unroll
        for (int d = 0; d < 32; d++) win[d] = xr[d];
    }
    s_v[tid] = win[31];

    // ---- projections + bf16 split -> smem (permuted granules) ----
    {
        u64 win2[16];
        #pragma unroll
        for (int i = 0; i < 16; i++) win2[i] = pack2(win[2 * i], win[2 * i + 1]);

        const float qscale = 0.17677669529663687f * 1.4426950408889634f; // (1/sqrt32)*log2(e)
        uint32_t qhp[16], qlp[16], khp[16], klp[16];
        #pragma unroll
        for (int s2 = 0; s2 < 16; s2++) {
            int sA = 2 * s2, sB = sA + 1;
            float qa = fmaxf(dot32(s_wq + sA * 32, win2) + s_bq[sA], 0.0f) * qscale;
            float qb = fmaxf(dot32(s_wq + sB * 32, win2) + s_bq[sB], 0.0f) * qscale;
            float ka = fmaxf(dot32(s_wk + sA * 32, win2) + s_bk[sA], 0.0f);
            float kb = fmaxf(dot32(s_wk + sB * 32, win2) + s_bk[sB], 0.0f);
            uint16_t h0, l0, h1, l1;
            bsplit(qa, h0, l0); bsplit(qb, h1, l1);
            qhp[s2] = (uint32_t)h0 | ((uint32_t)h1 << 16);
            qlp[s2] = (uint32_t)l0 | ((uint32_t)l1 << 16);
            bsplit(ka, h0, l0); bsplit(kb, h1, l1);
            khp[s2] = (uint32_t)h0 | ((uint32_t)h1 << 16);
            klp[s2] = (uint32_t)l0 | ((uint32_t)l1 << 16);
        }
        uint4* qhr = (uint4*)(QH + tid * ROWB);
        uint4* qlr = (uint4*)(QL + tid * ROWB);
        uint4* khr = (uint4*)(KH + tid * ROWB);
        uint4* klr = (uint4*)(KL + tid * ROWB);
        #pragma unroll
        for (int i = 0; i < 4; i++) {
            qhr[i] = make_uint4(qhp[i], qhp[i + 4], qhp[i + 8], qhp[i + 12]);
            qlr[i] = make_uint4(qlp[i], qlp[i + 4], qlp[i + 8], qlp[i + 12]);
            khr[i] = make_uint4(khp[i], khp[i + 4], khp[i + 8], khp[i + 12]);
            klr[i] = make_uint4(klp[i], klp[i + 4], klp[i + 8], klp[i + 12]);
        }
    }
    __syncthreads();

    // ---- A fragments, held whole loop: aqh/aql[mt][k2][reg] ----
    uint32_t aqh[2][2][4], aql[2][2][4];
    #pragma unroll
    for (int mt = 0; mt < 2; mt++) {
        uint32_t r0off = (uint32_t)(32 * w + 16 * mt + g) * ROWB + (uint32_t)cq * 16u;
        uint4 uh0 = *(const uint4*)(QH + r0off);
        uint4 uh1 = *(const uint4*)(QH + r0off + 8 * ROWB);
        uint4 ul0 = *(const uint4*)(QL + r0off);
        uint4 ul1 = *(const uint4*)(QL + r0off + 8 * ROWB);
        aqh[mt][0][0] = uh0.x; aqh[mt][0][1] = uh1.x; aqh[mt][0][2] = uh0.y; aqh[mt][0][3] = uh1.y;
        aqh[mt][1][0] = uh0.z; aqh[mt][1][1] = uh1.z; aqh[mt][1][2] = uh0.w; aqh[mt][1][3] = uh1.w;
        aql[mt][0][0] = ul0.x; aql[mt][0][1] = ul1.x; aql[mt][0][2] = ul0.y; aql[mt][0][3] = ul1.y;
        aql[mt][1][0] = ul0.z; aql[mt][1][1] = ul1.z; aql[mt][1][2] = ul0.w; aql[mt][1][3] = ul1.w;
    }

    float stM[4], stD[4], stN[4];
    #pragma unroll
    for (int r = 0; r < 4; r++) { stM[r] = -1e30f; stD[r] = 0.0f; stN[r] = 0.0f; }

    const char* KHg = KH + (uint32_t)g * ROWB + (uint32_t)cq * 16u;
    const char* KLg = KL + (uint32_t)g * ROWB + (uint32_t)cq * 16u;

    #pragma unroll 1
    for (int ch = 0; ch < 16; ch++) {
        uint4 bh[2], blo[2];
        #pragma unroll
        for (int nt = 0; nt < 2; nt++) {
            bh[nt]  = *(const uint4*)(KHg + ((uint32_t)ch * 16u + 8u * nt) * ROWB);
            blo[nt] = *(const uint4*)(KLg + ((uint32_t)ch * 16u + 8u * nt) * ROWB);
        }
        float2 v0 = *(const float2*)&s_v[16 * ch + 2 * cq];
        float2 v1 = *(const float2*)&s_v[16 * ch + 8 + 2 * cq];

        float acc[2][2][4];
        #pragma unroll
        for (int mt = 0; mt < 2; mt++)
            #pragma unroll
            for (int nt = 0; nt < 2; nt++) {
                float* a = acc[mt][nt];
                a[0] = a[1] = a[2] = a[3] = 0.0f;
                // qh*kh (k0,k1), qh*kl, ql*kh  — exact to ~1e-5
                mma16816(a, aqh[mt][0][0], aqh[mt][0][1], aqh[mt][0][2], aqh[mt][0][3], bh[nt].x,  bh[nt].y);
                mma16816(a, aqh[mt][1][0], aqh[mt][1][1], aqh[mt][1][2], aqh[mt][1][3], bh[nt].z,  bh[nt].w);
                mma16816(a, aqh[mt][0][0], aqh[mt][0][1], aqh[mt][0][2], aqh[mt][0][3], blo[nt].x, blo[nt].y);
                mma16816(a, aqh[mt][1][0], aqh[mt][1][1], aqh[mt][1][2], aqh[mt][1][3], blo[nt].z, blo[nt].w);
                mma16816(a, aql[mt][0][0], aql[mt][0][1], aql[mt][0][2], aql[mt][0][3], bh[nt].x,  bh[nt].y);
                mma16816(a, aql[mt][1][0], aql[mt][1][1], aql[mt][1][2], aql[mt][1][3], bh[nt].z,  bh[nt].w);
            }

        // flash update: 4 logical rows per thread, 4 cols each
        #pragma unroll
        for (int mt = 0; mt < 2; mt++)
            #pragma unroll
            for (int i = 0; i < 2; i++) {
                int r = mt * 2 + i;
                float s0 = acc[mt][0][2 * i + 0];
                float s1 = acc[mt][0][2 * i + 1];
                float s2 = acc[mt][1][2 * i + 0];
                float s3 = acc[mt][1][2 * i + 1];
                float mx = fmaxf(fmaxf(s0, s1), fmaxf(s2, s3));
                float Mn = fmaxf(stM[r], mx);
                float corr = ex2f(stM[r] - Mn);
                float e0 = ex2f(s0 - Mn);
                float e1 = ex2f(s1 - Mn);
                float e2 = ex2f(s2 - Mn);
                float e3 = ex2f(s3 - Mn);
                stD[r] = stD[r] * corr + ((e0 + e1) + (e2 + e3));
                stN[r] = stN[r] * corr + (e0 * v0.x + e1 * v0.y + e2 * v1.x + e3 * v1.y);
                stM[r] = Mn;
            }
    }

    // ---- quad merge (cols) + write ----
    #pragma unroll
    for (int r = 0; r < 4; r++) {
        #pragma unroll
        for (int off = 1; off <= 2; off <<= 1) {
            float pm = __shfl_xor_sync(0xffffffffu, stM[r], off);
            float pd = __shfl_xor_sync(0xffffffffu, stD[r], off);
            float pn = __shfl_xor_sync(0xffffffffu, stN[r], off);
            float M  = fmaxf(stM[r], pm);
            float ca = ex2f(stM[r] - M), cb = ex2f(pm - M);
            stD[r] = stD[r] * ca + pd * cb;
            stN[r] = stN[r] * ca + pn * cb;
            stM[r] = M;
        }
    }
    if (cq == 0) {
        #pragma unroll
        for (int r = 0; r < 4; r++) {
            int row = 32 * w + (r >> 1) * 16 + (r & 1) * 8 + g;
            out[((size_t)(b * 256 + row)) * TB + t] = s_v[row] + stN[r] / stD[r];
        }
    }
}

extern "C" void kernel_launch(void* const* d_in, const int* in_sizes, int n_in,
                              void* d_out, int out_size) {
    const float* x    = (const float*)d_in[0];
    const float* kw   = (const float*)d_in[1];
    const float* kb   = (const float*)d_in[2];
    const float* kg   = (const float*)d_in[3];
    const float* kbe  = (const float*)d_in[4];
    const float* qw   = (const float*)d_in[5];
    const float* qb   = (const float*)d_in[6];
    const float* qg   = (const float*)d_in[7];
    const float* qbe  = (const float*)d_in[8];
    float* o = (float*)d_out;

    cudaFuncSetAttribute(csa_mma_kernel, cudaFuncAttributeMaxDynamicSharedMemorySize, DSMEM_BYTES);
    dim3 grid(TB, BB);
    csa_mma_kernel<<<grid, 256, DSMEM_BYTES>>>(x, kw, kb, kg, kbe, qw, qb, qg, qbe, o);
}

// round 9
// speedup vs baseline: 1.7369x; 1.3862x over previous
#include <cuda_runtime.h>
#include <cuda_bf16.h>
#include <cstdint>

#define TB 1024
#define BB 4
#define ROWB 64u     // bytes per granule row: 32 bf16
#define XROW 33      // f32 staging row stride (floats), conflict-free

// dynamic smem layout (bytes)
#define OFF_FH   0u          // framed hi granules, 256x64  (overlays f32 staging buf)
#define OFF_FL   16384u      // framed lo granules
// f32 staging buffer = bytes [0, 33792) = 256 rows x 33 floats
#define OFF_QH   33792u
#define OFF_QL   50176u
#define OFF_KH   66560u
#define OFF_KL   82944u
#define OFF_WQH  99328u      // weight granules, 32 rows x 64B each
#define OFF_WQL  101376u
#define OFF_WKH  103424u
#define OFF_WKL  105472u
#define DSMEM_BYTES 107520

// Granule layout: row r = 4 x uint4; granule i, component j = bf16 pair (i+4j) = cols {2(i+4j), 2(i+4j)+1}.
// One LDS.128 at (row*64 + cq*16) gives a thread its m16n8k16 fragment regs for both K16 halves.

// ---------------- helpers ----------------
static __device__ __forceinline__ float ex2f(float v) {
    float y; asm("ex2.approx.ftz.f32 %0, %1;" : "=f"(y) : "f"(v)); return y;
}
// split pair (even,odd) into bf16 hi-pair and lo-pair words (even value in low 16 bits)
static __device__ __forceinline__ void psplit(float e, float o, uint32_t& hi, uint32_t& lo) {
    __nv_bfloat16 he = __float2bfloat16(e), ho = __float2bfloat16(o);
    __nv_bfloat162 hp(he, ho);
    hi = *reinterpret_cast<uint32_t*>(&hp);
    __nv_bfloat162 lp(__float2bfloat16(e - __bfloat162float(he)),
                      __float2bfloat16(o - __bfloat162float(ho)));
    lo = *reinterpret_cast<uint32_t*>(&lp);
}
// m16n8k16 row.col f32.bf16.bf16.f32, D += A*B
static __device__ __forceinline__ void mma16816(float* d, const uint32_t* a,
                                                uint32_t b0, uint32_t b1) {
    asm("mma.sync.aligned.m16n8k16.row.col.f32.bf16.bf16.f32 "
        "{%0,%1,%2,%3}, {%4,%5,%6,%7}, {%8,%9}, {%0,%1,%2,%3};"
        : "+f"(d[0]), "+f"(d[1]), "+f"(d[2]), "+f"(d[3])
        : "r"(a[0]), "r"(a[1]), "r"(a[2]), "r"(a[3]), "r"(b0), "r"(b1));
}

// ---------------- kernel ----------------
// One CTA per (b,t), 256 threads, 2 CTAs/SM. All GEMMs on HMMA.
// 1) stage x coalesced -> f32 buf; weight granules + biases (folded BN + qscale).
// 2) per-thread: split own framed row -> FH/FL granules (overlay after sync).
// 3) proj MMA: warp w -> h rows 32w..+31, 64 outputs; bias in acc; relu; psplit -> Q/K granules.
// 4) attention: warp w rows 32w..+31 x 256 cols, hi/lo 3-term MMA, register flash softmax.
__global__ void __launch_bounds__(256, 2)
csa_mma_kernel(const float* __restrict__ x,
               const float* __restrict__ kw,  const float* __restrict__ kbias,
               const float* __restrict__ kg,  const float* __restrict__ kbeta,
               const float* __restrict__ qw,  const float* __restrict__ qbias,
               const float* __restrict__ qg,  const float* __restrict__ qbeta,
               float* __restrict__ out)
{
    extern __shared__ char dsm[];
    __shared__ __align__(8) float s_v[256];
    __shared__ float s_bq[32], s_bk[32];

    float* s_x = (float*)dsm;                 // staging (overlaid by FH/FL later)
    char* FH = dsm + OFF_FH;  char* FL = dsm + OFF_FL;
    char* QH = dsm + OFF_QH;  char* QL = dsm + OFF_QL;
    char* KH = dsm + OFF_KH;  char* KL = dsm + OFF_KL;

    const int t   = blockIdx.x;
    const int b   = blockIdx.y;
    const int tid = threadIdx.x;
    const int w   = tid >> 5;
    const int l   = tid & 31;
    const int g   = l >> 2;    // fragment row group
    const int cq  = l & 3;     // quad col id (granule slot)

    const float inv    = rsqrtf(1.0f + 1e-5f);
    const float qscale = 0.17677669529663687f * 1.4426950408889634f; // (1/sqrt32)*log2(e)

    // ---- 1a. stage windows coalesced: lane = time offset ----
    {
        const float* xb = x + ((size_t)b * 256) * TB;
        #pragma unroll
        for (int i = tid; i < 256 * 32; i += 256) {
            int c = i >> 5, d = i & 31;
            int tau = t - 31 + d;
            s_x[c * XROW + d] = (tau >= 0) ? xb[(size_t)c * TB + tau] : 0.0f;
        }
    }

    // ---- 1b. weight granules (folded) + biases ----
    {
        const int m    = tid >> 7;          // 0 = q, 1 = k
        const int slot = tid & 127;
        const int s    = slot >> 2;
        const int i    = slot & 3;
        const float* wsrc = m ? kw : qw;
        const float* gsrc = m ? kg : qg;
        float gs = gsrc[s] * inv * (m ? 1.0f : qscale);
        uint32_t gh[4], gl[4];
        #pragma unroll
        for (int j = 0; j < 4; j++) {
            int d0 = 2 * (i + 4 * j);
            float2 wv = *(const float2*)(wsrc + s * 32 + d0);
            psplit(wv.x * gs, wv.y * gs, gh[j], gl[j]);
        }
        char* WH = dsm + (m ? OFF_WKH : OFF_WQH);
        char* WL = dsm + (m ? OFF_WKL : OFF_WQL);
        *(uint4*)(WH + s * 64 + i * 16) = make_uint4(gh[0], gh[1], gh[2], gh[3]);
        *(uint4*)(WL + s * 64 + i * 16) = make_uint4(gl[0], gl[1], gl[2], gl[3]);
        if (tid < 32)
            s_bq[tid] = (qbias[tid] * qg[tid] * inv + qbeta[tid]) * qscale;
        else if (tid < 64) {
            int ss = tid - 32;
            s_bk[ss] = kbias[ss] * kg[ss] * inv + kbeta[ss];
        }
    }
    __syncthreads();

    // ---- 2. split own framed row -> granule regs; overlay-store after sync ----
    uint32_t fh[4][4], fl[4][4];   // [granule i][comp j]
    {
        const float* xr = s_x + tid * XROW;
        float f[32];
        #pragma unroll
        for (int d = 0; d < 32; d++) f[d] = xr[d];
        s_v[tid] = f[31];
        #pragma unroll
        for (int i = 0; i < 4; i++)
            #pragma unroll
            for (int j = 0; j < 4; j++) {
                int d0 = 2 * (i + 4 * j);
                psplit(f[d0], f[d0 + 1], fh[i][j], fl[i][j]);
            }
    }
    __syncthreads();   // all staging reads done before overlay writes
    {
        uint4* dh = (uint4*)(FH + tid * ROWB);
        uint4* dl = (uint4*)(FL + tid * ROWB);
        #pragma unroll
        for (int i = 0; i < 4; i++) {
            dh[i] = make_uint4(fh[i][0], fh[i][1], fh[i][2], fh[i][3]);
            dl[i] = make_uint4(fl[i][0], fl[i][1], fl[i][2], fl[i][3]);
        }
    }
    __syncthreads();

    // ---- 3. projection MMA ----
    {
        // A fragments: framed rows 32w+16mt+{g,g+8}
        uint32_t ah[2][2][4], al[2][2][4];
        #pragma unroll
        for (int mt = 0; mt < 2; mt++) {
            uint32_t r0 = (uint32_t)(32 * w + 16 * mt + g) * ROWB + (uint32_t)cq * 16u;
            uint4 h0 = *(const uint4*)(FH + r0);
            uint4 h1 = *(const uint4*)(FH + r0 + 8 * ROWB);
            uint4 l0 = *(const uint4*)(FL + r0);
            uint4 l1 = *(const uint4*)(FL + r0 + 8 * ROWB);
            ah[mt][0][0] = h0.x; ah[mt][0][1] = h1.x; ah[mt][0][2] = h0.y; ah[mt][0][3] = h1.y;
            ah[mt][1][0] = h0.z; ah[mt][1][1] = h1.z; ah[mt][1][2] = h0.w; ah[mt][1][3] = h1.w;
            al[mt][0][0] = l0.x; al[mt][0][1] = l1.x; al[mt][0][2] = l0.y; al[mt][0][3] = l1.y;
            al[mt][1][0] = l0.z; al[mt][1][1] = l1.z; al[mt][1][2] = l0.w; al[mt][1][3] = l1.w;
        }

        #pragma unroll
        for (int m = 0; m < 2; m++) {      // 0 = q, 1 = k
            const char* WH = dsm + (m ? OFF_WKH : OFF_WQH);
            const char* WL = dsm + (m ? OFF_WKL : OFF_WQL);
            const float* bias = m ? s_bk : s_bq;
            uint32_t oh[4][4], ol[4][4];   // [row r = 2mt+i][comp nt]
            #pragma unroll
            for (int nt = 0; nt < 4; nt++) {
                uint32_t woff = (uint32_t)(8 * nt + g) * ROWB + (uint32_t)cq * 16u;
                uint4 wh = *(const uint4*)(WH + woff);
                uint4 wl = *(const uint4*)(WL + woff);
                float2 bb = *(const float2*)(bias + 8 * nt + 2 * cq);
                #pragma unroll
                for (int mt = 0; mt < 2; mt++) {
                    float a4[4] = {bb.x, bb.y, bb.x, bb.y};
                    mma16816(a4, ah[mt][0], wh.x, wh.y);   // fh*wh k0
                    mma16816(a4, ah[mt][1], wh.z, wh.w);   // fh*wh k1
                    mma16816(a4, ah[mt][0], wl.x, wl.y);   // fh*wl
                    mma16816(a4, ah[mt][1], wl.z, wl.w);
                    mma16816(a4, al[mt][0], wh.x, wh.y);   // fl*wh
                    mma16816(a4, al[mt][1], wh.z, wh.w);
                    #pragma unroll
                    for (int i = 0; i < 2; i++) {
                        float ve = fmaxf(a4[2 * i + 0], 0.0f);
                        float vo = fmaxf(a4[2 * i + 1], 0.0f);
                        psplit(ve, vo, oh[mt * 2 + i][nt], ol[mt * 2 + i][nt]);
                    }
                }
            }
            char* DH = m ? KH : QH;
            char* DL = m ? KL : QL;
            #pragma unroll
            for (int r = 0; r < 4; r++) {
                int row = 32 * w + 16 * (r >> 1) + 8 * (r & 1) + g;
                uint32_t off = (uint32_t)row * ROWB + (uint32_t)cq * 16u;
                *(uint4*)(DH + off) = make_uint4(oh[r][0], oh[r][1], oh[r][2], oh[r][3]);
                *(uint4*)(DL + off) = make_uint4(ol[r][0], ol[r][1], ol[r][2], ol[r][3]);
            }
        }
    }
    __syncthreads();

    // ---- 4. attention: A fragments from Q granules ----
    uint32_t aqh[2][2][4], aql[2][2][4];
    #pragma unroll
    for (int mt = 0; mt < 2; mt++) {
        uint32_t r0 = (uint32_t)(32 * w + 16 * mt + g) * ROWB + (uint32_t)cq * 16u;
        uint4 uh0 = *(const uint4*)(QH + r0);
        uint4 uh1 = *(const uint4*)(QH + r0 + 8 * ROWB);
        uint4 ul0 = *(const uint4*)(QL + r0);
        uint4 ul1 = *(const uint4*)(QL + r0 + 8 * ROWB);
        aqh[mt][0][0] = uh0.x; aqh[mt][0][1] = uh1.x; aqh[mt][0][2] = uh0.y; aqh[mt][0][3] = uh1.y;
        aqh[mt][1][0] = uh0.z; aqh[mt][1][1] = uh1.z; aqh[mt][1][2] = uh0.w; aqh[mt][1][3] = uh1.w;
        aql[mt][0][0] = ul0.x; aql[mt][0][1] = ul1.x; aql[mt][0][2] = ul0.y; aql[mt][0][3] = ul1.y;
        aql[mt][1][0] = ul0.z; aql[mt][1][1] = ul1.z; aql[mt][1][2] = ul0.w; aql[mt][1][3] = ul1.w;
    }

    float stM[4], stD[4], stN[4];
    #pragma unroll
    for (int r = 0; r < 4; r++) { stM[r] = -1e30f; stD[r] = 0.0f; stN[r] = 0.0f; }

    const char* KHg = KH + (uint32_t)g * ROWB + (uint32_t)cq * 16u;
    const char* KLg = KL + (uint32_t)g * ROWB + (uint32_t)cq * 16u;

    #pragma unroll 1
    for (int ch = 0; ch < 16; ch++) {
        uint4 bh[2], blo[2];
        #pragma unroll
        for (int nt = 0; nt < 2; nt++) {
            bh[nt]  = *(const uint4*)(KHg + ((uint32_t)ch * 16u + 8u * nt) * ROWB);
            blo[nt] = *(const uint4*)(KLg + ((uint32_t)ch * 16u + 8u * nt) * ROWB);
        }
        float2 v0 = *(const float2*)&s_v[16 * ch + 2 * cq];
        float2 v1 = *(const float2*)&s_v[16 * ch + 8 + 2 * cq];

        float acc[2][2][4];
        #pragma unroll
        for (int mt = 0; mt < 2; mt++)
            #pragma unroll
            for (int nt = 0; nt < 2; nt++) {
                float* a = acc[mt][nt];
                a[0] = a[1] = a[2] = a[3] = 0.0f;
                mma16816(a, aqh[mt][0], bh[nt].x,  bh[nt].y);
                mma16816(a, aqh[mt][1], bh[nt].z,  bh[nt].w);
                mma16816(a, aqh[mt][0], blo[nt].x, blo[nt].y);
                mma16816(a, aqh[mt][1], blo[nt].z, blo[nt].w);
                mma16816(a, aql[mt][0], bh[nt].x,  bh[nt].y);
                mma16816(a, aql[mt][1], bh[nt].z,  bh[nt].w);
            }

        #pragma unroll
        for (int mt = 0; mt < 2; mt++)
            #pragma unroll
            for (int i = 0; i < 2; i++) {
                int r = mt * 2 + i;
                float s0 = acc[mt][0][2 * i + 0];
                float s1 = acc[mt][0][2 * i + 1];
                float s2 = acc[mt][1][2 * i + 0];
                float s3 = acc[mt][1][2 * i + 1];
                float mx = fmaxf(fmaxf(s0, s1), fmaxf(s2, s3));
                float Mn = fmaxf(stM[r], mx);
                float corr = ex2f(stM[r] - Mn);
                float e0 = ex2f(s0 - Mn);
                float e1 = ex2f(s1 - Mn);
                float e2 = ex2f(s2 - Mn);
                float e3 = ex2f(s3 - Mn);
                stD[r] = stD[r] * corr + ((e0 + e1) + (e2 + e3));
                stN[r] = stN[r] * corr + (e0 * v0.x + e1 * v0.y + e2 * v1.x + e3 * v1.y);
                stM[r] = Mn;
            }
    }

    // ---- quad merge (cols) + write ----
    #pragma unroll
    for (int r = 0; r < 4; r++) {
        #pragma unroll
        for (int off = 1; off <= 2; off <<= 1) {
            float pm = __shfl_xor_sync(0xffffffffu, stM[r], off);
            float pd = __shfl_xor_sync(0xffffffffu, stD[r], off);
            float pn = __shfl_xor_sync(0xffffffffu, stN[r], off);
            float M  = fmaxf(stM[r], pm);
            float ca = ex2f(stM[r] - M), cb = ex2f(pm - M);
            stD[r] = stD[r] * ca + pd * cb;
            stN[r] = stN[r] * ca + pn * cb;
            stM[r] = M;
        }
    }
    if (cq == 0) {
        #pragma unroll
        for (int r = 0; r < 4; r++) {
            int row = 32 * w + (r >> 1) * 16 + (r & 1) * 8 + g;
            out[((size_t)(b * 256 + row)) * TB + t] = s_v[row] + stN[r] / stD[r];
        }
    }
}

extern "C" void kernel_launch(void* const* d_in, const int* in_sizes, int n_in,
                              void* d_out, int out_size) {
    const float* x    = (const float*)d_in[0];
    const float* kw   = (const float*)d_in[1];
    const float* kb   = (const float*)d_in[2];
    const float* kg   = (const float*)d_in[3];
    const float* kbe  = (const float*)d_in[4];
    const float* qw   = (const float*)d_in[5];
    const float* qb   = (const float*)d_in[6];
    const float* qg   = (const float*)d_in[7];
    const float* qbe  = (const float*)d_in[8];
    float* o = (float*)d_out;

    cudaFuncSetAttribute(csa_mma_kernel, cudaFuncAttributeMaxDynamicSharedMemorySize, DSMEM_BYTES);
    dim3 grid(TB, BB);
    csa_mma_kernel<<<grid, 256, DSMEM_BYTES>>>(x, kw, kb, kg, kbe, qw, qb, qg, qbe, o);
}

// round 10
// speedup vs baseline: 1.8968x; 1.0921x over previous
#include <cuda_runtime.h>
#include <cuda_bf16.h>
#include <cstdint>

#define TB 1024
#define BB 4
#define ROWB 64u     // bytes per granule row: 32 bf16
#define XROW 33      // f32 staging row stride (floats), conflict-free

// dynamic smem layout (bytes); staging f32 buf = [0, 33792) overlays FH/FL
#define OFF_FH   0u
#define OFF_FL   16384u
#define OFF_KH   33792u
#define OFF_KL   50176u
#define OFF_WQH  66560u
#define OFF_WQL  68608u
#define OFF_WKH  70656u
#define OFF_WKL  72704u
#define DSMEM_BYTES 74752

// Granule layout: row r = 4 x uint4; slot s comp j = bf16 pair (s+4j) = cols {2(s+4j), 2(s+4j)+1}.

// ---------------- helpers ----------------
static __device__ __forceinline__ float ex2f(float v) {
    float y; asm("ex2.approx.ftz.f32 %0, %1;" : "=f"(y) : "f"(v)); return y;
}
static __device__ __forceinline__ void psplit(float e, float o, uint32_t& hi, uint32_t& lo) {
    __nv_bfloat16 he = __float2bfloat16(e), ho = __float2bfloat16(o);
    __nv_bfloat162 hp(he, ho);
    hi = *reinterpret_cast<uint32_t*>(&hp);
    __nv_bfloat162 lp(__float2bfloat16(e - __bfloat162float(he)),
                      __float2bfloat16(o - __bfloat162float(ho)));
    lo = *reinterpret_cast<uint32_t*>(&lp);
}
static __device__ __forceinline__ void mma16816(float* d, const uint32_t* a,
                                                uint32_t b0, uint32_t b1) {
    asm("mma.sync.aligned.m16n8k16.row.col.f32.bf16.bf16.f32 "
        "{%0,%1,%2,%3}, {%4,%5,%6,%7}, {%8,%9}, {%0,%1,%2,%3};"
        : "+f"(d[0]), "+f"(d[1]), "+f"(d[2]), "+f"(d[3])
        : "r"(a[0]), "r"(a[1]), "r"(a[2]), "r"(a[3]), "r"(b0), "r"(b1));
}

// ---------------- kernel ----------------
// One CTA per (b,t), 256 threads, 2 CTAs/SM. All GEMMs on HMMA.
// Q projection outputs stay in registers as attention A-fragments (no smem round-trip):
// proj C-frag (rows {g,g+8}, col pair 8nt+2cq) == attention A-frag (k2=nt>>1, half=nt&1).
__global__ void __launch_bounds__(256, 2)
csa_mma_kernel(const float* __restrict__ x,
               const float* __restrict__ kw,  const float* __restrict__ kbias,
               const float* __restrict__ kg,  const float* __restrict__ kbeta,
               const float* __restrict__ qw,  const float* __restrict__ qbias,
               const float* __restrict__ qg,  const float* __restrict__ qbeta,
               float* __restrict__ out)
{
    extern __shared__ char dsm[];
    __shared__ __align__(8) float s_v[256];
    __shared__ float s_bq[32], s_bk[32];

    float* s_x = (float*)dsm;                 // staging (overlaid by FH/FL later)
    char* FH = dsm + OFF_FH;  char* FL = dsm + OFF_FL;
    char* KH = dsm + OFF_KH;  char* KL = dsm + OFF_KL;

    const int t   = blockIdx.x;
    const int b   = blockIdx.y;
    const int tid = threadIdx.x;
    const int w   = tid >> 5;
    const int l   = tid & 31;
    const int g   = l >> 2;    // fragment row group
    const int cq  = l & 3;     // quad col id (granule slot)

    const float inv    = rsqrtf(1.0f + 1e-5f);
    const float qscale = 0.17677669529663687f * 1.4426950408889634f; // (1/sqrt32)*log2(e)

    // ---- 1a. stage windows coalesced: lane = time offset ----
    {
        const float* xb = x + ((size_t)b * 256) * TB;
        #pragma unroll
        for (int i = tid; i < 256 * 32; i += 256) {
            int c = i >> 5, d = i & 31;
            int tau = t - 31 + d;
            s_x[c * XROW + d] = (tau >= 0) ? xb[(size_t)c * TB + tau] : 0.0f;
        }
    }

    // ---- 1b. weight granules (folded BN; qscale folded into q) + biases ----
    {
        const int m    = tid >> 7;          // 0 = q, 1 = k
        const int slot = tid & 127;
        const int s    = slot >> 2;
        const int i    = slot & 3;
        const float* wsrc = m ? kw : qw;
        const float* gsrc = m ? kg : qg;
        float gs = gsrc[s] * inv * (m ? 1.0f : qscale);
        uint32_t gh[4], gl[4];
        #pragma unroll
        for (int j = 0; j < 4; j++) {
            int d0 = 2 * (i + 4 * j);
            float2 wv = *(const float2*)(wsrc + s * 32 + d0);
            psplit(wv.x * gs, wv.y * gs, gh[j], gl[j]);
        }
        char* WH = dsm + (m ? OFF_WKH : OFF_WQH);
        char* WL = dsm + (m ? OFF_WKL : OFF_WQL);
        *(uint4*)(WH + s * 64 + i * 16) = make_uint4(gh[0], gh[1], gh[2], gh[3]);
        *(uint4*)(WL + s * 64 + i * 16) = make_uint4(gl[0], gl[1], gl[2], gl[3]);
        if (tid < 32)
            s_bq[tid] = (qbias[tid] * qg[tid] * inv + qbeta[tid]) * qscale;
        else if (tid < 64) {
            int ss = tid - 32;
            s_bk[ss] = kbias[ss] * kg[ss] * inv + kbeta[ss];
        }
    }
    __syncthreads();

    // ---- 2. split own framed row -> granule regs; overlay-store after sync ----
    uint32_t fh[4][4], fl[4][4];
    {
        const float* xr = s_x + tid * XROW;
        float f[32];
        #pragma unroll
        for (int d = 0; d < 32; d++) f[d] = xr[d];
        s_v[tid] = f[31];
        #pragma unroll
        for (int i = 0; i < 4; i++)
            #pragma unroll
            for (int j = 0; j < 4; j++) {
                int d0 = 2 * (i + 4 * j);
                psplit(f[d0], f[d0 + 1], fh[i][j], fl[i][j]);
            }
    }
    __syncthreads();
    {
        uint4* dh = (uint4*)(FH + tid * ROWB);
        uint4* dl = (uint4*)(FL + tid * ROWB);
        #pragma unroll
        for (int i = 0; i < 4; i++) {
            dh[i] = make_uint4(fh[i][0], fh[i][1], fh[i][2], fh[i][3]);
            dl[i] = make_uint4(fl[i][0], fl[i][1], fl[i][2], fl[i][3]);
        }
    }
    __syncthreads();

    // ---- 3. projection MMA ----
    uint32_t aqh[2][2][4], aql[2][2][4];   // attention A-frags, filled by q-proj
    {
        uint32_t ah[2][2][4], al[2][2][4];
        #pragma unroll
        for (int mt = 0; mt < 2; mt++) {
            uint32_t r0 = (uint32_t)(32 * w + 16 * mt + g) * ROWB + (uint32_t)cq * 16u;
            uint4 h0 = *(const uint4*)(FH + r0);
            uint4 h1 = *(const uint4*)(FH + r0 + 8 * ROWB);
            uint4 l0 = *(const uint4*)(FL + r0);
            uint4 l1 = *(const uint4*)(FL + r0 + 8 * ROWB);
            ah[mt][0][0] = h0.x; ah[mt][0][1] = h1.x; ah[mt][0][2] = h0.y; ah[mt][0][3] = h1.y;
            ah[mt][1][0] = h0.z; ah[mt][1][1] = h1.z; ah[mt][1][2] = h0.w; ah[mt][1][3] = h1.w;
            al[mt][0][0] = l0.x; al[mt][0][1] = l1.x; al[mt][0][2] = l0.y; al[mt][0][3] = l1.y;
            al[mt][1][0] = l0.z; al[mt][1][1] = l1.z; al[mt][1][2] = l0.w; al[mt][1][3] = l1.w;
        }

        // q: outputs straight into A-fragment registers
        {
            const char* WH = dsm + OFF_WQH;
            const char* WL = dsm + OFF_WQL;
            #pragma unroll
            for (int nt = 0; nt < 4; nt++) {
                uint32_t woff = (uint32_t)(8 * nt + g) * ROWB + (uint32_t)cq * 16u;
                uint4 wh = *(const uint4*)(WH + woff);
                uint4 wl = *(const uint4*)(WL + woff);
                float2 bb = *(const float2*)(s_bq + 8 * nt + 2 * cq);
                #pragma unroll
                for (int mt = 0; mt < 2; mt++) {
                    float a4[4] = {bb.x, bb.y, bb.x, bb.y};
                    mma16816(a4, ah[mt][0], wh.x, wh.y);
                    mma16816(a4, ah[mt][1], wh.z, wh.w);
                    mma16816(a4, ah[mt][0], wl.x, wl.y);
                    mma16816(a4, ah[mt][1], wl.z, wl.w);
                    mma16816(a4, al[mt][0], wh.x, wh.y);
                    mma16816(a4, al[mt][1], wh.z, wh.w);
                    const int k2 = nt >> 1, hx = 2 * (nt & 1);
                    psplit(fmaxf(a4[0], 0.0f), fmaxf(a4[1], 0.0f),
                           aqh[mt][k2][hx + 0], aql[mt][k2][hx + 0]);   // row g
                    psplit(fmaxf(a4[2], 0.0f), fmaxf(a4[3], 0.0f),
                           aqh[mt][k2][hx + 1], aql[mt][k2][hx + 1]);   // row g+8
                }
            }
        }

        // k: outputs -> smem granules
        {
            const char* WH = dsm + OFF_WKH;
            const char* WL = dsm + OFF_WKL;
            uint32_t oh[4][4], ol[4][4];
            #pragma unroll
            for (int nt = 0; nt < 4; nt++) {
                uint32_t woff = (uint32_t)(8 * nt + g) * ROWB + (uint32_t)cq * 16u;
                uint4 wh = *(const uint4*)(WH + woff);
                uint4 wl = *(const uint4*)(WL + woff);
                float2 bb = *(const float2*)(s_bk + 8 * nt + 2 * cq);
                #pragma unroll
                for (int mt = 0; mt < 2; mt++) {
                    float a4[4] = {bb.x, bb.y, bb.x, bb.y};
                    mma16816(a4, ah[mt][0], wh.x, wh.y);
                    mma16816(a4, ah[mt][1], wh.z, wh.w);
                    mma16816(a4, ah[mt][0], wl.x, wl.y);
                    mma16816(a4, ah[mt][1], wl.z, wl.w);
                    mma16816(a4, al[mt][0], wh.x, wh.y);
                    mma16816(a4, al[mt][1], wh.z, wh.w);
                    #pragma unroll
                    for (int i = 0; i < 2; i++)
                        psplit(fmaxf(a4[2 * i + 0], 0.0f), fmaxf(a4[2 * i + 1], 0.0f),
                               oh[mt * 2 + i][nt], ol[mt * 2 + i][nt]);
                }
            }
            #pragma unroll
            for (int r = 0; r < 4; r++) {
                int row = 32 * w + 16 * (r >> 1) + 8 * (r & 1) + g;
                uint32_t off = (uint32_t)row * ROWB + (uint32_t)cq * 16u;
                *(uint4*)(KH + off) = make_uint4(oh[r][0], oh[r][1], oh[r][2], oh[r][3]);
                *(uint4*)(KL + off) = make_uint4(ol[r][0], ol[r][1], ol[r][2], ol[r][3]);
            }
        }
    }
    __syncthreads();

    // ---- 4. attention ----
    float stM[4], stD[4], stN[4];
    #pragma unroll
    for (int r = 0; r < 4; r++) { stM[r] = -1e30f; stD[r] = 0.0f; stN[r] = 0.0f; }

    const char* KHg = KH + (uint32_t)g * ROWB + (uint32_t)cq * 16u;
    const char* KLg = KL + (uint32_t)g * ROWB + (uint32_t)cq * 16u;

    #pragma unroll 2
    for (int ch = 0; ch < 16; ch++) {
        uint4 bh[2], blo[2];
        #pragma unroll
        for (int nt = 0; nt < 2; nt++) {
            bh[nt]  = *(const uint4*)(KHg + ((uint32_t)ch * 16u + 8u * nt) * ROWB);
            blo[nt] = *(const uint4*)(KLg + ((uint32_t)ch * 16u + 8u * nt) * ROWB);
        }
        float2 v0 = *(const float2*)&s_v[16 * ch + 2 * cq];
        float2 v1 = *(const float2*)&s_v[16 * ch + 8 + 2 * cq];

        float acc[2][2][4];
        #pragma unroll
        for (int mt = 0; mt < 2; mt++)
            #pragma unroll
            for (int nt = 0; nt < 2; nt++) {
                float* a = acc[mt][nt];
                a[0] = a[1] = a[2] = a[3] = 0.0f;
                mma16816(a, aqh[mt][0], bh[nt].x,  bh[nt].y);
                mma16816(a, aqh[mt][1], bh[nt].z,  bh[nt].w);
                mma16816(a, aqh[mt][0], blo[nt].x, blo[nt].y);
                mma16816(a, aqh[mt][1], blo[nt].z, blo[nt].w);
                mma16816(a, aql[mt][0], bh[nt].x,  bh[nt].y);
                mma16816(a, aql[mt][1], bh[nt].z,  bh[nt].w);
            }

        #pragma unroll
        for (int mt = 0; mt < 2; mt++)
            #pragma unroll
            for (int i = 0; i < 2; i++) {
                int r = mt * 2 + i;
                float s0 = acc[mt][0][2 * i + 0];
                float s1 = acc[mt][0][2 * i + 1];
                float s2 = acc[mt][1][2 * i + 0];
                float s3 = acc[mt][1][2 * i + 1];
                float mx = fmaxf(fmaxf(s0, s1), fmaxf(s2, s3));
                float Mn = fmaxf(stM[r], mx);
                float corr = ex2f(stM[r] - Mn);
                float e0 = ex2f(s0 - Mn);
                float e1 = ex2f(s1 - Mn);
                float e2 = ex2f(s2 - Mn);
                float e3 = ex2f(s3 - Mn);
                stD[r] = stD[r] * corr + ((e0 + e1) + (e2 + e3));
                stN[r] = stN[r] * corr + (e0 * v0.x + e1 * v0.y + e2 * v1.x + e3 * v1.y);
                stM[r] = Mn;
            }
    }

    // ---- quad merge (cols) + write ----
    #pragma unroll
    for (int r = 0; r < 4; r++) {
        #pragma unroll
        for (int off = 1; off <= 2; off <<= 1) {
            float pm = __shfl_xor_sync(0xffffffffu, stM[r], off);
            float pd = __shfl_xor_sync(0xffffffffu, stD[r], off);
            float pn = __shfl_xor_sync(0xffffffffu, stN[r], off);
            float M  = fmaxf(stM[r], pm);
            float ca = ex2f(stM[r] - M), cb = ex2f(pm - M);
            stD[r] = stD[r] * ca + pd * cb;
            stN[r] = stN[r] * ca + pn * cb;
            stM[r] = M;
        }
    }
    if (cq == 0) {
        #pragma unroll
        for (int r = 0; r < 4; r++) {
            int row = 32 * w + (r >> 1) * 16 + (r & 1) * 8 + g;
            out[((size_t)(b * 256 + row)) * TB + t] = s_v[row] + stN[r] / stD[r];
        }
    }
}

extern "C" void kernel_launch(void* const* d_in, const int* in_sizes, int n_in,
                              void* d_out, int out_size) {
    const float* x    = (const float*)d_in[0];
    const float* kw   = (const float*)d_in[1];
    const float* kb   = (const float*)d_in[2];
    const float* kg   = (const float*)d_in[3];
    const float* kbe  = (const float*)d_in[4];
    const float* qw   = (const float*)d_in[5];
    const float* qb   = (const float*)d_in[6];
    const float* qg   = (const float*)d_in[7];
    const float* qbe  = (const float*)d_in[8];
    float* o = (float*)d_out;

    cudaFuncSetAttribute(csa_mma_kernel, cudaFuncAttributeMaxDynamicSharedMemorySize, DSMEM_BYTES);
    dim3 grid(TB, BB);
    csa_mma_kernel<<<grid, 256, DSMEM_BYTES>>>(x, kw, kb, kg, kbe, qw, qb, qg, qbe, o);
}

// round 11
// speedup vs baseline: 2.1147x; 1.1149x over previous
#include <cuda_runtime.h>
#include <cuda_bf16.h>
#include <cstdint>

#define TB 1024
#define BB 4
#define ROWB 64u     // bytes per granule row: 32 bf16
#define XROW 33      // f32 staging row stride (floats), conflict-free

// dynamic smem layout (bytes); staging f32 buf = [0, 33792) overlays FH/FL
#define OFF_FH   0u
#define OFF_FL   16384u
#define OFF_KH   33792u
#define OFF_KL   50176u
#define OFF_WQH  66560u
#define OFF_WQL  68608u
#define OFF_WKH  70656u
#define OFF_WKL  72704u
#define DSMEM_BYTES 74752

// Granule layout: row r = 4 x uint4; slot s comp j = bf16 pair (s+4j) = cols {2(s+4j), 2(s+4j)+1}.

// ---------------- helpers ----------------
static __device__ __forceinline__ float ex2f(float v) {
    float y; asm("ex2.approx.ftz.f32 %0, %1;" : "=f"(y) : "f"(v)); return y;
}
static __device__ __forceinline__ void psplit(float e, float o, uint32_t& hi, uint32_t& lo) {
    __nv_bfloat16 he = __float2bfloat16(e), ho = __float2bfloat16(o);
    __nv_bfloat162 hp(he, ho);
    hi = *reinterpret_cast<uint32_t*>(&hp);
    __nv_bfloat162 lp(__float2bfloat16(e - __bfloat162float(he)),
                      __float2bfloat16(o - __bfloat162float(ho)));
    lo = *reinterpret_cast<uint32_t*>(&lp);
}
static __device__ __forceinline__ void mma16816(float* d, const uint32_t* a,
                                                uint32_t b0, uint32_t b1) {
    asm("mma.sync.aligned.m16n8k16.row.col.f32.bf16.bf16.f32 "
        "{%0,%1,%2,%3}, {%4,%5,%6,%7}, {%8,%9}, {%0,%1,%2,%3};"
        : "+f"(d[0]), "+f"(d[1]), "+f"(d[2]), "+f"(d[3])
        : "r"(a[0]), "r"(a[1]), "r"(a[2]), "r"(a[3]), "r"(b0), "r"(b1));
}

// ---------------- kernel ----------------
// One CTA per (b,t), 256 threads, 2 CTAs/SM. All GEMMs on HMMA.
// Softmax WITHOUT running max: logits >= 0 (relu(q).relu(k) dot), scored in log2
// domain with constant shift -32 baked into the MMA accumulator init. Exponent
// shift is exact; den/num are pure accumulators -> chunks fully parallel.
__global__ void __launch_bounds__(256, 2)
csa_mma_kernel(const float* __restrict__ x,
               const float* __restrict__ kw,  const float* __restrict__ kbias,
               const float* __restrict__ kg,  const float* __restrict__ kbeta,
               const float* __restrict__ qw,  const float* __restrict__ qbias,
               const float* __restrict__ qg,  const float* __restrict__ qbeta,
               float* __restrict__ out)
{
    extern __shared__ char dsm[];
    __shared__ __align__(8) float s_v[256];
    __shared__ float s_bq[32], s_bk[32];

    float* s_x = (float*)dsm;                 // staging (overlaid by FH/FL later)
    char* FH = dsm + OFF_FH;  char* FL = dsm + OFF_FL;
    char* KH = dsm + OFF_KH;  char* KL = dsm + OFF_KL;

    const int t   = blockIdx.x;
    const int b   = blockIdx.y;
    const int tid = threadIdx.x;
    const int w   = tid >> 5;
    const int l   = tid & 31;
    const int g   = l >> 2;    // fragment row group
    const int cq  = l & 3;     // quad col id (granule slot)

    const float inv    = rsqrtf(1.0f + 1e-5f);
    const float qscale = 0.17677669529663687f * 1.4426950408889634f; // (1/sqrt32)*log2(e)

    // ---- 1a. stage windows coalesced: lane = time offset ----
    {
        const float* xb = x + ((size_t)b * 256) * TB;
        #pragma unroll
        for (int i = tid; i < 256 * 32; i += 256) {
            int c = i >> 5, d = i & 31;
            int tau = t - 31 + d;
            s_x[c * XROW + d] = (tau >= 0) ? xb[(size_t)c * TB + tau] : 0.0f;
        }
    }

    // ---- 1b. weight granules (folded BN; qscale folded into q) + biases ----
    {
        const int m    = tid >> 7;          // 0 = q, 1 = k
        const int slot = tid & 127;
        const int s    = slot >> 2;
        const int i    = slot & 3;
        const float* wsrc = m ? kw : qw;
        const float* gsrc = m ? kg : qg;
        float gs = gsrc[s] * inv * (m ? 1.0f : qscale);
        uint32_t gh[4], gl[4];
        #pragma unroll
        for (int j = 0; j < 4; j++) {
            int d0 = 2 * (i + 4 * j);
            float2 wv = *(const float2*)(wsrc + s * 32 + d0);
            psplit(wv.x * gs, wv.y * gs, gh[j], gl[j]);
        }
        char* WH = dsm + (m ? OFF_WKH : OFF_WQH);
        char* WL = dsm + (m ? OFF_WKL : OFF_WQL);
        *(uint4*)(WH + s * 64 + i * 16) = make_uint4(gh[0], gh[1], gh[2], gh[3]);
        *(uint4*)(WL + s * 64 + i * 16) = make_uint4(gl[0], gl[1], gl[2], gl[3]);
        if (tid < 32)
            s_bq[tid] = (qbias[tid] * qg[tid] * inv + qbeta[tid]) * qscale;
        else if (tid < 64) {
            int ss = tid - 32;
            s_bk[ss] = kbias[ss] * kg[ss] * inv + kbeta[ss];
        }
    }
    __syncthreads();

    // ---- 2. split own framed row -> granule regs; overlay-store after sync ----
    uint32_t fh[4][4], fl[4][4];
    {
        const float* xr = s_x + tid * XROW;
        float f[32];
        #pragma unroll
        for (int d = 0; d < 32; d++) f[d] = xr[d];
        s_v[tid] = f[31];
        #pragma unroll
        for (int i = 0; i < 4; i++)
            #pragma unroll
            for (int j = 0; j < 4; j++) {
                int d0 = 2 * (i + 4 * j);
                psplit(f[d0], f[d0 + 1], fh[i][j], fl[i][j]);
            }
    }
    __syncthreads();
    {
        uint4* dh = (uint4*)(FH + tid * ROWB);
        uint4* dl = (uint4*)(FL + tid * ROWB);
        #pragma unroll
        for (int i = 0; i < 4; i++) {
            dh[i] = make_uint4(fh[i][0], fh[i][1], fh[i][2], fh[i][3]);
            dl[i] = make_uint4(fl[i][0], fl[i][1], fl[i][2], fl[i][3]);
        }
    }
    __syncthreads();

    // ---- 3. projection MMA ----
    uint32_t aqh[2][2][4], aql[2][2][4];   // attention A-frags, filled by q-proj
    {
        uint32_t ah[2][2][4], al[2][2][4];
        #pragma unroll
        for (int mt = 0; mt < 2; mt++) {
            uint32_t r0 = (uint32_t)(32 * w + 16 * mt + g) * ROWB + (uint32_t)cq * 16u;
            uint4 h0 = *(const uint4*)(FH + r0);
            uint4 h1 = *(const uint4*)(FH + r0 + 8 * ROWB);
            uint4 l0 = *(const uint4*)(FL + r0);
            uint4 l1 = *(const uint4*)(FL + r0 + 8 * ROWB);
            ah[mt][0][0] = h0.x; ah[mt][0][1] = h1.x; ah[mt][0][2] = h0.y; ah[mt][0][3] = h1.y;
            ah[mt][1][0] = h0.z; ah[mt][1][1] = h1.z; ah[mt][1][2] = h0.w; ah[mt][1][3] = h1.w;
            al[mt][0][0] = l0.x; al[mt][0][1] = l1.x; al[mt][0][2] = l0.y; al[mt][0][3] = l1.y;
            al[mt][1][0] = l0.z; al[mt][1][1] = l1.z; al[mt][1][2] = l0.w; al[mt][1][3] = l1.w;
        }

        // q: outputs straight into A-fragment registers
        {
            const char* WH = dsm + OFF_WQH;
            const char* WL = dsm + OFF_WQL;
            #pragma unroll
            for (int nt = 0; nt < 4; nt++) {
                uint32_t woff = (uint32_t)(8 * nt + g) * ROWB + (uint32_t)cq * 16u;
                uint4 wh = *(const uint4*)(WH + woff);
                uint4 wl = *(const uint4*)(WL + woff);
                float2 bb = *(const float2*)(s_bq + 8 * nt + 2 * cq);
                #pragma unroll
                for (int mt = 0; mt < 2; mt++) {
                    float a4[4] = {bb.x, bb.y, bb.x, bb.y};
                    mma16816(a4, ah[mt][0], wh.x, wh.y);
                    mma16816(a4, ah[mt][1], wh.z, wh.w);
                    mma16816(a4, ah[mt][0], wl.x, wl.y);
                    mma16816(a4, ah[mt][1], wl.z, wl.w);
                    mma16816(a4, al[mt][0], wh.x, wh.y);
                    mma16816(a4, al[mt][1], wh.z, wh.w);
                    const int k2 = nt >> 1, hx = 2 * (nt & 1);
                    psplit(fmaxf(a4[0], 0.0f), fmaxf(a4[1], 0.0f),
                           aqh[mt][k2][hx + 0], aql[mt][k2][hx + 0]);   // row g
                    psplit(fmaxf(a4[2], 0.0f), fmaxf(a4[3], 0.0f),
                           aqh[mt][k2][hx + 1], aql[mt][k2][hx + 1]);   // row g+8
                }
            }
        }

        // k: outputs -> smem granules
        {
            const char* WH = dsm + OFF_WKH;
            const char* WL = dsm + OFF_WKL;
            uint32_t oh[4][4], ol[4][4];
            #pragma unroll
            for (int nt = 0; nt < 4; nt++) {
                uint32_t woff = (uint32_t)(8 * nt + g) * ROWB + (uint32_t)cq * 16u;
                uint4 wh = *(const uint4*)(WH + woff);
                uint4 wl = *(const uint4*)(WL + woff);
                float2 bb = *(const float2*)(s_bk + 8 * nt + 2 * cq);
                #pragma unroll
                for (int mt = 0; mt < 2; mt++) {
                    float a4[4] = {bb.x, bb.y, bb.x, bb.y};
                    mma16816(a4, ah[mt][0], wh.x, wh.y);
                    mma16816(a4, ah[mt][1], wh.z, wh.w);
                    mma16816(a4, ah[mt][0], wl.x, wl.y);
                    mma16816(a4, ah[mt][1], wl.z, wl.w);
                    mma16816(a4, al[mt][0], wh.x, wh.y);
                    mma16816(a4, al[mt][1], wh.z, wh.w);
                    #pragma unroll
                    for (int i = 0; i < 2; i++)
                        psplit(fmaxf(a4[2 * i + 0], 0.0f), fmaxf(a4[2 * i + 1], 0.0f),
                               oh[mt * 2 + i][nt], ol[mt * 2 + i][nt]);
                }
            }
            #pragma unroll
            for (int r = 0; r < 4; r++) {
                int row = 32 * w + 16 * (r >> 1) + 8 * (r & 1) + g;
                uint32_t off = (uint32_t)row * ROWB + (uint32_t)cq * 16u;
                *(uint4*)(KH + off) = make_uint4(oh[r][0], oh[r][1], oh[r][2], oh[r][3]);
                *(uint4*)(KL + off) = make_uint4(ol[r][0], ol[r][1], ol[r][2], ol[r][3]);
            }
        }
    }
    __syncthreads();

    // ---- 4. attention: no running max; acc initialized to -32 (exact shift) ----
    float stD[4], stN[4];
    #pragma unroll
    for (int r = 0; r < 4; r++) { stD[r] = 0.0f; stN[r] = 0.0f; }

    const char* KHg = KH + (uint32_t)g * ROWB + (uint32_t)cq * 16u;
    const char* KLg = KL + (uint32_t)g * ROWB + (uint32_t)cq * 16u;

    #pragma unroll 4
    for (int ch = 0; ch < 16; ch++) {
        uint4 bh[2], blo[2];
        #pragma unroll
        for (int nt = 0; nt < 2; nt++) {
            bh[nt]  = *(const uint4*)(KHg + ((uint32_t)ch * 16u + 8u * nt) * ROWB);
            blo[nt] = *(const uint4*)(KLg + ((uint32_t)ch * 16u + 8u * nt) * ROWB);
        }
        float2 v0 = *(const float2*)&s_v[16 * ch + 2 * cq];
        float2 v1 = *(const float2*)&s_v[16 * ch + 8 + 2 * cq];

        float acc[2][2][4];
        #pragma unroll
        for (int mt = 0; mt < 2; mt++)
            #pragma unroll
            for (int nt = 0; nt < 2; nt++) {
                float* a = acc[mt][nt];
                a[0] = a[1] = a[2] = a[3] = -32.0f;   // constant softmax shift
                mma16816(a, aqh[mt][0], bh[nt].x,  bh[nt].y);
                mma16816(a, aqh[mt][1], bh[nt].z,  bh[nt].w);
                mma16816(a, aqh[mt][0], blo[nt].x, blo[nt].y);
                mma16816(a, aqh[mt][1], blo[nt].z, blo[nt].w);
                mma16816(a, aql[mt][0], bh[nt].x,  bh[nt].y);
                mma16816(a, aql[mt][1], bh[nt].z,  bh[nt].w);
            }

        #pragma unroll
        for (int mt = 0; mt < 2; mt++)
            #pragma unroll
            for (int i = 0; i < 2; i++) {
                int r = mt * 2 + i;
                float e0 = ex2f(acc[mt][0][2 * i + 0]);
                float e1 = ex2f(acc[mt][0][2 * i + 1]);
                float e2 = ex2f(acc[mt][1][2 * i + 0]);
                float e3 = ex2f(acc[mt][1][2 * i + 1]);
                stD[r] += (e0 + e1) + (e2 + e3);
                stN[r] += (e0 * v0.x + e1 * v0.y) + (e2 * v1.x + e3 * v1.y);
            }
    }

    // ---- quad merge (pure adds) + write ----
    #pragma unroll
    for (int r = 0; r < 4; r++) {
        #pragma unroll
        for (int off = 1; off <= 2; off <<= 1) {
            stD[r] += __shfl_xor_sync(0xffffffffu, stD[r], off);
            stN[r] += __shfl_xor_sync(0xffffffffu, stN[r], off);
        }
    }
    if (cq == 0) {
        #pragma unroll
        for (int r = 0; r < 4; r++) {
            int row = 32 * w + (r >> 1) * 16 + (r & 1) * 8 + g;
            out[((size_t)(b * 256 + row)) * TB + t] = s_v[row] + stN[r] / stD[r];
        }
    }
}

extern "C" void kernel_launch(void* const* d_in, const int* in_sizes, int n_in,
                              void* d_out, int out_size) {
    const float* x    = (const float*)d_in[0];
    const float* kw   = (const float*)d_in[1];
    const float* kb   = (const float*)d_in[2];
    const float* kg   = (const float*)d_in[3];
    const float* kbe  = (const float*)d_in[4];
    const float* qw   = (const float*)d_in[5];
    const float* qb   = (const float*)d_in[6];
    const float* qg   = (const float*)d_in[7];
    const float* qbe  = (const float*)d_in[8];
    float* o = (float*)d_out;

    cudaFuncSetAttribute(csa_mma_kernel, cudaFuncAttributeMaxDynamicSharedMemorySize, DSMEM_BYTES);
    dim3 grid(TB, BB);
    csa_mma_kernel<<<grid, 256, DSMEM_BYTES>>>(x, kw, kb, kg, kbe, qw, qb, qg, qbe, o);
}